// round 6
// baseline (speedup 1.0000x reference)
#include <cuda_runtime.h>

#define K 48
#define STOPID 47
#define CHUNK 16
#define CLAMPV 1e32f

typedef unsigned long long ull;

// ---------- packed f32x2 helpers (Blackwell sm_103a) ----------
__device__ __forceinline__ ull pack2(float x, float y) {
    ull r;
    asm("mov.b64 %0, {%1, %2};" : "=l"(r)
        : "r"(__float_as_uint(x)), "r"(__float_as_uint(y)));
    return r;
}
__device__ __forceinline__ void unpack2(ull v, float& x, float& y) {
    unsigned int a, b;
    asm("mov.b64 {%0, %1}, %2;" : "=r"(a), "=r"(b) : "l"(v));
    x = __uint_as_float(a);
    y = __uint_as_float(b);
}
__device__ __forceinline__ ull fma2(ull a, ull b, ull c) {
    ull d;
    asm("fma.rn.f32x2 %0, %1, %2, %3;" : "=l"(d) : "l"(a), "l"(b), "l"(c));
    return d;
}
__device__ __forceinline__ ull add2(ull a, ull b) {
    ull d;
    asm("add.rn.f32x2 %0, %1, %2;" : "=l"(d) : "l"(a), "l"(b));
    return d;
}
__device__ __forceinline__ void cp_async16(unsigned int s, const void* g) {
    asm volatile("cp.async.cg.shared.global [%0], [%1], 16;" :: "r"(s), "l"(g));
}

// TWO sequences per warp (independent recurrence chains interleaved so each
// chain's dependency stalls are filled by the other's issue). E = exp(trans)
// lives in 96 packed-f32x2 registers SHARED by both chains. State kept in
// probability space: p' = exp(emit) * (E p); exp(emit) comes from cp.async
// double-buffered 16-step chunks, off the serial chain. Renorm every 8 steps.
// 2 warps/CTA (block=64) x 128 CTAs -> 256 warps, 4 sequences per SM.
__global__ __launch_bounds__(64, 1) void crf_fwd_kernel(
    const float* __restrict__ h_tag,   // [B, T, K]
    const float* __restrict__ mask,    // [B, T]
    const float* __restrict__ trans,   // [K, K]
    float* __restrict__ out,           // [B]
    int B, int T)
{
    __shared__ __align__(16) float emb[2][2][2][CHUNK * K]; // [warp][seq][buf]
    __shared__ __align__(16) float mkb[2][2][2][CHUNK];
    __shared__ __align__(16) float pb [2][2][2][K];         // p exchange

    const int w    = threadIdx.x >> 5;
    const int lane = threadIdx.x & 31;
    const int b0   = blockIdx.x * 4 + w * 2;
    if (b0 >= B) return;
    const int  b1     = (b0 + 1 < B) ? b0 + 1 : b0;   // duplicate if ragged
    const bool write1 = (b0 + 1 < B);

    const bool act  = lane < 24;
    const int  row0 = 2 * lane;

    // ---- E packed across j: E2a[q] = (E[i0][2q], E[i0][2q+1]) for row i0=2*lane
    ull E2a[24], E2b[24];
    if (act) {
        const float* t0 = trans + row0 * K;
        const float* t1 = t0 + K;
#pragma unroll
        for (int q = 0; q < 24; q++) {
            E2a[q] = pack2(__expf(t0[2 * q]), __expf(t0[2 * q + 1]));
            E2b[q] = pack2(__expf(t1[2 * q]), __expf(t1[2 * q + 1]));
        }
    } else {
#pragma unroll
        for (int q = 0; q < 24; q++) { E2a[q] = 0ULL; E2b[q] = 0ULL; }
    }

    const float* hb0 = h_tag + (size_t)b0 * T * K;
    const float* hb1 = h_tag + (size_t)b1 * T * K;
    const float* mb0 = mask + (size_t)b0 * T;
    const float* mb1 = mask + (size_t)b1 * T;

    // init: score = NEG except STOP=0 -> c=-1e4, p=1 on normal states,
    // p_STOP clamped at 1e32 (feeds only the PAD track, e^~4000 below the
    // answer — validated at rel_err 4e-6 in R3/R4).
    float pA0, pA1, cA = -1.0e4f;
    float pB0, pB1, cB = -1.0e4f;
    if (act) {
        pA0 = 1.0f; pA1 = (row0 + 1 == STOPID) ? CLAMPV : 1.0f;
        pB0 = 1.0f; pB1 = pA1;
    } else { pA0 = pA1 = pB0 = pB1 = 0.0f; }
    if (act) {
        *(float2*)(&pb[w][0][0][row0]) = make_float2(pA0, pA1);
        *(float2*)(&pb[w][1][0][row0]) = make_float2(pB0, pB1);
    }

    const int nc = (T + CHUNK - 1) / CHUNK;

    // ---- chunk prefetch (both sequences)
    auto prefetch = [&](int ch) {
        const int t0n = ch * CHUNK;
        const int nb  = ch & 1;
        const size_t base = (size_t)t0n * K;
        unsigned int se0 = (unsigned int)__cvta_generic_to_shared(&emb[w][0][nb][0]);
        unsigned int se1 = (unsigned int)__cvta_generic_to_shared(&emb[w][1][nb][0]);
#pragma unroll
        for (int i = 0; i < 6; i++) {
            int seg = lane + 32 * i;
            if (base + (size_t)(seg + 1) * 4 <= (size_t)T * K) {
                cp_async16(se0 + seg * 16, hb0 + base + seg * 4);
                cp_async16(se1 + seg * 16, hb1 + base + seg * 4);
            }
        }
        unsigned int sm0 = (unsigned int)__cvta_generic_to_shared(&mkb[w][0][nb][0]);
        unsigned int sm1 = (unsigned int)__cvta_generic_to_shared(&mkb[w][1][nb][0]);
        if (lane < 4 && t0n + (lane + 1) * 4 <= T) {
            cp_async16(sm0 + lane * 16, mb0 + t0n + lane * 4);
            cp_async16(sm1 + lane * 16, mb1 + t0n + lane * 4);
        }
        asm volatile("cp.async.commit_group;");
    };

    prefetch(0);

    int t = 0;
    for (int ch = 0; ch < nc; ch++) {
        const int cb = ch & 1;
        if (ch + 1 < nc) {
            prefetch(ch + 1);
            asm volatile("cp.async.wait_group 1;");
        } else {
            asm volatile("cp.async.wait_group 0;");
        }

        const int steps = min(CHUNK, T - ch * CHUNK);
        for (int s = 0; s < steps; s++, t++) {
            __syncwarp();   // chunk + previous p visible

            const int eo = s * K + (act ? row0 : 0);
            float2 emA = *(const float2*)(&emb[w][0][cb][eo]);
            float2 emB = *(const float2*)(&emb[w][1][cb][eo]);
            float exA0 = __expf(emA.x), exA1 = __expf(emA.y);
            float exB0 = __expf(emB.x), exB1 = __expf(emB.y);
            float mkA = mkb[w][0][cb][s];
            float mkB = mkb[w][1][cb][s];

            // two interleaved matvecs: 24 LDS.128 + 96 fma2
            const ulonglong2* puA = (const ulonglong2*)(&pb[w][0][t & 1][0]);
            const ulonglong2* puB = (const ulonglong2*)(&pb[w][1][t & 1][0]);
            ull aA0 = 0, aA1 = 0, bA0 = 0, bA1 = 0;   // seq A: even/odd row accs
            ull aB0 = 0, aB1 = 0, bB0 = 0, bB1 = 0;   // seq B
#pragma unroll
            for (int m = 0; m < 12; m++) {
                ulonglong2 uA = puA[m];
                ulonglong2 uB = puB[m];
                aA0 = fma2(E2a[2 * m],     uA.x, aA0);
                aB0 = fma2(E2a[2 * m],     uB.x, aB0);
                bA0 = fma2(E2b[2 * m],     uA.x, bA0);
                bB0 = fma2(E2b[2 * m],     uB.x, bB0);
                aA1 = fma2(E2a[2 * m + 1], uA.y, aA1);
                aB1 = fma2(E2a[2 * m + 1], uB.y, aB1);
                bA1 = fma2(E2b[2 * m + 1], uA.y, bA1);
                bB1 = fma2(E2b[2 * m + 1], uB.y, bB1);
            }
            ull sA0 = add2(aA0, aA1), sA1 = add2(bA0, bA1);
            ull sB0 = add2(aB0, aB1), sB1 = add2(bB0, bB1);
            float xA0, yA0, xA1, yA1, xB0, yB0, xB1, yB1;
            unpack2(sA0, xA0, yA0); unpack2(sA1, xA1, yA1);
            unpack2(sB0, xB0, yB0); unpack2(sB1, xB1, yB1);

            float nA0 = fminf(exA0 * (xA0 + yA0), CLAMPV);
            float nA1 = fminf(exA1 * (xA1 + yA1), CLAMPV);
            float nB0 = fminf(exB0 * (xB0 + yB0), CLAMPV);
            float nB1 = fminf(exB1 * (xB1 + yB1), CLAMPV);

            bool uA = (mkA != 0.0f), uB = (mkB != 0.0f);
            pA0 = uA ? nA0 : pA0;  pA1 = uA ? nA1 : pA1;
            pB0 = uB ? nB0 : pB0;  pB1 = uB ? nB1 : pB1;

            if ((t & 7) == 7) {   // renorm (growth ~4.4/step; e^88 headroom)
                float dA = __shfl_sync(0xffffffffu, pA0, 0);
                float dB = __shfl_sync(0xffffffffu, pB0, 0);
                float rA, rB;
                asm("rcp.approx.f32 %0, %1;" : "=f"(rA) : "f"(dA));
                asm("rcp.approx.f32 %0, %1;" : "=f"(rB) : "f"(dB));
                pA0 *= rA; pA1 *= rA; cA += __logf(dA);
                pB0 *= rB; pB1 *= rB; cB += __logf(dB);
            }

            if (act) {
                *(float2*)(&pb[w][0][(t + 1) & 1][row0]) = make_float2(pA0, pA1);
                *(float2*)(&pb[w][1][(t + 1) & 1][row0]) = make_float2(pB0, pB1);
            }
        }
    }

    // ---- finalize: out = c + log( sum_k p_k * exp(trans[STOP][k]) )
    float vA = 0.0f, vB = 0.0f;
    if (act) {
        float e0 = __expf(trans[STOPID * K + row0]);
        float e1 = __expf(trans[STOPID * K + row0 + 1]);
        vA = pA0 * e0 + pA1 * e1;
        vB = pB0 * e0 + pB1 * e1;
    }
#pragma unroll
    for (int o = 16; o; o >>= 1) {
        vA += __shfl_xor_sync(0xffffffffu, vA, o);
        vB += __shfl_xor_sync(0xffffffffu, vB, o);
    }
    if (lane == 0) {
        out[b0] = cA + __logf(vA);
        if (write1) out[b1] = cB + __logf(vB);
    }
}

extern "C" void kernel_launch(void* const* d_in, const int* in_sizes, int n_in,
                              void* d_out, int out_size)
{
    // Identify inputs by size: h_tag = largest, trans = smallest, mask = other
    int iH = 0, iT = 0;
    for (int i = 1; i < 3; i++) {
        if (in_sizes[i] > in_sizes[iH]) iH = i;
        if (in_sizes[i] < in_sizes[iT]) iT = i;
    }
    int iM = 3 - iH - iT;

    const float* h_tag = (const float*)d_in[iH];
    const float* mask  = (const float*)d_in[iM];
    const float* trans = (const float*)d_in[iT];
    float* out = (float*)d_out;

    int B = out_size;             // 512
    int T = in_sizes[iM] / B;     // 1024

    dim3 block(64);               // 2 warps -> 2 SMSPs, 4 sequences per CTA
    dim3 grid((B + 3) / 4);
    crf_fwd_kernel<<<grid, block>>>(h_tag, mask, trans, out, B, T);
}

// round 7
// speedup vs baseline: 1.6595x; 1.6595x over previous
#include <cuda_runtime.h>

#define K 48
#define STOPID 47
#define CHUNK 16
#define NWARP 4
#define CLAMPV 1e32f

typedef unsigned long long ull;

// ---------- packed f32x2 helpers (Blackwell sm_103a) ----------
__device__ __forceinline__ ull pack2(float x, float y) {
    ull r;
    asm("mov.b64 %0, {%1, %2};" : "=l"(r)
        : "r"(__float_as_uint(x)), "r"(__float_as_uint(y)));
    return r;
}
__device__ __forceinline__ void unpack2(ull v, float& x, float& y) {
    unsigned int a, b;
    asm("mov.b64 {%0, %1}, %2;" : "=r"(a), "=r"(b) : "l"(v));
    x = __uint_as_float(a);
    y = __uint_as_float(b);
}
__device__ __forceinline__ ull fma2(ull a, ull b, ull c) {
    ull d;
    asm("fma.rn.f32x2 %0, %1, %2, %3;" : "=l"(d) : "l"(a), "l"(b), "l"(c));
    return d;
}
__device__ __forceinline__ ull add2(ull a, ull b) {
    ull d;
    asm("add.rn.f32x2 %0, %1, %2;" : "=l"(d) : "l"(a), "l"(b));
    return d;
}
__device__ __forceinline__ void cp_async16(unsigned int s, const void* g) {
    asm volatile("cp.async.cg.shared.global [%0], [%1], 16;" :: "r"(s), "l"(g));
}

// One warp per sequence, ALL 32 lanes active: the 48x48 matvec is split into
// 96 half-rows (row r, j in [0,24) or [24,48)); lane l<16 owns lo-halves of
// rows 3l..3l+2, lane l+16 owns the hi-halves. Per lane: 36 fma2 (vs 48 with
// the 24-lane layout) and 6 LDS.128. Halves combined with one shfl_xor(16)
// per row. State in probability space: p' = exp(emit) * (E p), E = exp(trans)
// in 36 packed regs/lane. Emissions via cp.async double-buffered 16-step
// chunks (off the serial chain). Renorm every 8 steps.
__global__ __launch_bounds__(128, 1) void crf_fwd_kernel(
    const float* __restrict__ h_tag,   // [B, T, K]
    const float* __restrict__ mask,    // [B, T]
    const float* __restrict__ trans,   // [K, K]
    float* __restrict__ out,           // [B]
    int B, int T)
{
    __shared__ __align__(16) float emb[NWARP][2][CHUNK * K];  // emit chunks
    __shared__ __align__(16) float mkb[NWARP][2][CHUNK];      // mask chunks
    __shared__ __align__(16) float pb [NWARP][2][K];          // p exchange

    const int w    = threadIdx.x >> 5;
    const int lane = threadIdx.x & 31;
    const int b    = blockIdx.x * NWARP + w;
    if (b >= B) return;

    const int l16   = lane & 15;
    const int row0  = 3 * l16;            // this lane's rows: row0..row0+2
    const int jbase = (lane >> 4) * 24;   // lo half: j 0..23, hi half: j 24..47

    // E2[r][m] = ( exp(trans[row0+r][jbase+2m]), exp(trans[row0+r][jbase+2m+1]) )
    ull E2[3][12];
#pragma unroll
    for (int r = 0; r < 3; r++) {
        const float* tr = trans + (row0 + r) * K + jbase;
#pragma unroll
        for (int m = 0; m < 12; m++)
            E2[r][m] = pack2(__expf(tr[2 * m]), __expf(tr[2 * m + 1]));
    }

    const float* hb = h_tag + (size_t)b * T * K;
    const float* mb = mask + (size_t)b * T;

    // init: score = NEG except STOP=0 -> c=-1e4, p=1 normal, p_STOP clamped
    // to 1e32 (truncation feeds only the PAD track, ~e^4000 below the answer;
    // validated at rel_err 4e-6 in R3/R4/R5).
    float pr[3], c = -1.0e4f;
#pragma unroll
    for (int r = 0; r < 3; r++)
        pr[r] = (row0 + r == STOPID) ? CLAMPV : 1.0f;
    if (lane < 16) {
#pragma unroll
        for (int r = 0; r < 3; r++) pb[w][0][row0 + r] = pr[r];
    }

    const int nc = (T + CHUNK - 1) / CHUNK;

    auto prefetch = [&](int ch) {
        const int t0n = ch * CHUNK;
        const int nb  = ch & 1;
        const size_t base = (size_t)t0n * K;
        unsigned int se = (unsigned int)__cvta_generic_to_shared(&emb[w][nb][0]);
#pragma unroll
        for (int i = 0; i < 6; i++) {
            int seg = lane + 32 * i;
            if (base + (size_t)(seg + 1) * 4 <= (size_t)T * K)
                cp_async16(se + seg * 16, hb + base + seg * 4);
        }
        unsigned int sm = (unsigned int)__cvta_generic_to_shared(&mkb[w][nb][0]);
        if (lane < 4 && t0n + (lane + 1) * 4 <= T)
            cp_async16(sm + lane * 16, mb + t0n + lane * 4);
        asm volatile("cp.async.commit_group;");
    };

    prefetch(0);

    int t = 0;
    for (int ch = 0; ch < nc; ch++) {
        const int cb = ch & 1;
        if (ch + 1 < nc) {
            prefetch(ch + 1);
            asm volatile("cp.async.wait_group 1;");
        } else {
            asm volatile("cp.async.wait_group 0;");
        }

        const int steps = min(CHUNK, T - ch * CHUNK);
        for (int s = 0; s < steps; s++, t++) {
            __syncwarp();   // chunk data + previous step's p visible

            // off-chain: emissions + mask
            const float* eb = &emb[w][cb][s * K + row0];
            float ex0 = __expf(eb[0]);
            float ex1 = __expf(eb[1]);
            float ex2 = __expf(eb[2]);
            float mk  = mkb[w][cb][s];

            // half-matvec: 6 LDS.128 + 36 fma2
            const ulonglong2* pu =
                (const ulonglong2*)(&pb[w][t & 1][jbase]);
            ull a00 = 0, a01 = 0, a10 = 0, a11 = 0, a20 = 0, a21 = 0;
#pragma unroll
            for (int i = 0; i < 6; i++) {
                ulonglong2 u = pu[i];
                a00 = fma2(E2[0][2 * i],     u.x, a00);
                a10 = fma2(E2[1][2 * i],     u.x, a10);
                a20 = fma2(E2[2][2 * i],     u.x, a20);
                a01 = fma2(E2[0][2 * i + 1], u.y, a01);
                a11 = fma2(E2[1][2 * i + 1], u.y, a11);
                a21 = fma2(E2[2][2 * i + 1], u.y, a21);
            }
            float x, y, s0, s1, s2;
            unpack2(add2(a00, a01), x, y); s0 = x + y;
            unpack2(add2(a10, a11), x, y); s1 = x + y;
            unpack2(add2(a20, a21), x, y); s2 = x + y;

            // combine lo/hi halves across the lane groups
            s0 += __shfl_xor_sync(0xffffffffu, s0, 16);
            s1 += __shfl_xor_sync(0xffffffffu, s1, 16);
            s2 += __shfl_xor_sync(0xffffffffu, s2, 16);

            float n0 = fminf(ex0 * s0, CLAMPV);
            float n1 = fminf(ex1 * s1, CLAMPV);
            float n2 = fminf(ex2 * s2, CLAMPV);

            bool upd = (mk != 0.0f);
            pr[0] = upd ? n0 : pr[0];
            pr[1] = upd ? n1 : pr[1];
            pr[2] = upd ? n2 : pr[2];

            // renorm every 8 steps (growth ~4.4/step; e^88 headroom)
            if ((t & 7) == 7) {
                float d = __shfl_sync(0xffffffffu, pr[0], 0); // row 0: finite >0
                float sc;
                asm("rcp.approx.f32 %0, %1;" : "=f"(sc) : "f"(d));
                pr[0] *= sc; pr[1] *= sc; pr[2] *= sc;
                c += __logf(d);
            }

            if (lane < 16) {
                float* pd = &pb[w][(t + 1) & 1][row0];
                pd[0] = pr[0]; pd[1] = pr[1]; pd[2] = pr[2];
            }
        }
    }

    // finalize: out = c + log( sum_k p_k * exp(trans[STOP][k]) )
    float v = 0.0f;
    if (lane < 16) {
        const float* ts = trans + STOPID * K + row0;
        v = pr[0] * __expf(ts[0]) + pr[1] * __expf(ts[1]) + pr[2] * __expf(ts[2]);
    }
#pragma unroll
    for (int o = 16; o; o >>= 1)
        v += __shfl_xor_sync(0xffffffffu, v, o);
    if (lane == 0) out[b] = c + __logf(v);
}

extern "C" void kernel_launch(void* const* d_in, const int* in_sizes, int n_in,
                              void* d_out, int out_size)
{
    // Identify inputs by size: h_tag = largest, trans = smallest, mask = other
    int iH = 0, iT = 0;
    for (int i = 1; i < 3; i++) {
        if (in_sizes[i] > in_sizes[iH]) iH = i;
        if (in_sizes[i] < in_sizes[iT]) iT = i;
    }
    int iM = 3 - iH - iT;

    const float* h_tag = (const float*)d_in[iH];
    const float* mask  = (const float*)d_in[iM];
    const float* trans = (const float*)d_in[iT];
    float* out = (float*)d_out;

    int B = out_size;             // 512
    int T = in_sizes[iM] / B;     // 1024

    dim3 block(128);              // 4 warps -> all 4 SMSPs, 1 sequence/warp
    dim3 grid((B + NWARP - 1) / NWARP);
    crf_fwd_kernel<<<grid, block>>>(h_tag, mask, trans, out, B, T);
}